// round 1
// baseline (speedup 1.0000x reference)
#include <cuda_runtime.h>
#include <math.h>

#define D 4096
#define BB 512          // batch
#define N3 (3*D)

// ---------------- device scratch (no allocations allowed) ----------------
__device__ float g_h[BB*D];
__device__ float g_nt[(size_t)BB*N3];
__device__ float g_ma[BB*D];        // mod_alpha
__device__ float g_as[BB*D];        // softmax(prev_act)
__device__ float g_ars[BB*D];       // softmax(prev_rec_act)
__device__ float g_gsum[D];
__device__ float g_sdec[D];
__device__ float g_rmW[D], g_rsW[D], g_rmR[D], g_rsR[D];
__device__ float g_Wn[(size_t)D*D];
__device__ float g_Wrn[(size_t)D*D];
__device__ float g_rec[BB*D];
__device__ float g_recin[BB*D];
__device__ float g_act[BB*D];

// ---------------- block reduce ----------------
__device__ __forceinline__ float blk_reduce(float v, bool do_max) {
    __shared__ float sh[32];
    int lane = threadIdx.x & 31, w = threadIdx.x >> 5;
#pragma unroll
    for (int o = 16; o; o >>= 1) {
        float t = __shfl_xor_sync(0xffffffffu, v, o);
        v = do_max ? fmaxf(v, t) : v + t;
    }
    if (lane == 0) sh[w] = v;
    __syncthreads();
    int nw = (blockDim.x + 31) >> 5;
    if (w == 0) {
        v = (lane < nw) ? sh[lane] : (do_max ? -INFINITY : 0.f);
#pragma unroll
        for (int o = 16; o; o >>= 1) {
            float t = __shfl_xor_sync(0xffffffffu, v, o);
            v = do_max ? fmaxf(v, t) : v + t;
        }
        if (lane == 0) sh[0] = v;
    }
    __syncthreads();
    float r = sh[0];
    __syncthreads();   // allow sh reuse by next call
    return r;
}

// ---------------- row softmax (one block per row) ----------------
__global__ void row_softmax_kernel(const float* __restrict__ src, float* __restrict__ dst) {
    int row = blockIdx.x;
    const float* x = src + (size_t)row * D;
    float m = -INFINITY;
    for (int i = threadIdx.x; i < D; i += blockDim.x) m = fmaxf(m, x[i]);
    m = blk_reduce(m, true);
    float s = 0.f;
    for (int i = threadIdx.x; i < D; i += blockDim.x) s += expf(x[i] - m);
    s = blk_reduce(s, false);
    float inv = 1.f / s;
    for (int i = threadIdx.x; i < D; i += blockDim.x)
        dst[(size_t)row * D + i] = expf(x[i] - m) * inv;
}

// ---------------- per-row max & exp-sum for W softmax ----------------
__global__ void row_stats_kernel(const float* __restrict__ Wsrc,
                                 float* __restrict__ rmax, float* __restrict__ rsum) {
    int row = blockIdx.x;
    const float* x = Wsrc + (size_t)row * D;
    float m = -INFINITY;
    for (int i = threadIdx.x; i < D; i += blockDim.x) m = fmaxf(m, x[i]);
    m = blk_reduce(m, true);
    float s = 0.f;
    for (int i = threadIdx.x; i < D; i += blockDim.x) s += expf(x[i] - m);
    s = blk_reduce(s, false);
    if (threadIdx.x == 0) { rmax[row] = m; rsum[row] = s; }
}

// ---------------- layernorm (one block per row) ----------------
__global__ void layernorm_kernel(const float* __restrict__ src,
                                 const float* __restrict__ g, const float* __restrict__ b,
                                 float* __restrict__ dst) {
    int row = blockIdx.x;
    const float* x = src + (size_t)row * D;
    float s = 0.f, s2 = 0.f;
    for (int i = threadIdx.x; i < D; i += blockDim.x) { float v = x[i]; s += v; s2 += v * v; }
    s = blk_reduce(s, false);
    s2 = blk_reduce(s2, false);
    float mean = s * (1.f / D);
    float var = s2 * (1.f / D) - mean * mean;
    float rstd = rsqrtf(var + 1e-5f);
    for (int i = threadIdx.x; i < D; i += blockDim.x)
        dst[(size_t)row * D + i] = (x[i] - mean) * rstd * g[i] + b[i];
}

// ---------------- neuromodulators ----------------
__global__ void zero_kernel(float* p, int n) {
    int i = blockIdx.x * blockDim.x + threadIdx.x;
    if (i < n) p[i] = 0.f;
}

__device__ __forceinline__ float sigm(float x) { return 1.f / (1.f + expf(-x)); }

// grid (D/256, 8): each block covers 256 columns x 64 batch rows
__global__ void neuromod_partial(const float* __restrict__ nt,
                                 const float* __restrict__ dopamine,
                                 const float* __restrict__ serotonin,
                                 const float* __restrict__ gaba,
                                 const float* __restrict__ alpha,
                                 float* __restrict__ mod_alpha,
                                 float* __restrict__ gsum) {
    int j = blockIdx.x * blockDim.x + threadIdx.x;
    int b0 = blockIdx.y * (BB / 8);
    float a = alpha[j];
    float gs = 0.f;
    for (int b = b0; b < b0 + BB / 8; b++) {
        const float* p = nt + (size_t)b * N3 + 3 * j;
        float pd = p[0], ps = p[1], pg = p[2];
        float inv = 1.f / fmaxf(ps, 1e-6f);
        size_t bi = (size_t)b * D + j;
        float dop = tanhf(dopamine[bi] + pd * inv);
        float ser = sigm(serotonin[bi] + ps);
        float gab = sigm(gaba[bi] + pg * inv);
        gs += gab;
        mod_alpha[bi] = a * dop * ser;
    }
    atomicAdd(&gsum[j], gs);
}

__global__ void sdecay_kernel(const float* __restrict__ gsum,
                              const float* __restrict__ decay,
                              float* __restrict__ sdec) {
    int j = blockIdx.x * blockDim.x + threadIdx.x;
    sdec[j] = decay[j] * sigm(gsum[j] * (1.f / BB));
}

// ---------------- generic tiled SGEMM ----------------
// LAYOUT: 0 = NT (A[M,K], B[N,K]), 1 = NN (A[M,K], B[K,N]), 2 = TN (A[K,M], B[K,N])
// EPI:    0 = store, 1 = +bias relu, 2 = +bias, 3 = +addmat relu, 4 = Hebbian W update
template<int BM, int BN, int BK, int TM, int TN, int LAYOUT, int EPI>
__global__ void __launch_bounds__(256)
gemm_kernel(const float* __restrict__ A, const float* __restrict__ B,
            float* __restrict__ C, int M, int N, int K,
            const float* __restrict__ bias, const float* __restrict__ addmat,
            const float* __restrict__ Wold, const float* __restrict__ rmax,
            const float* __restrict__ rsum, const float* __restrict__ sdecay) {
    constexpr int THREADS = (BM / TM) * (BN / TN);
    constexpr int TX = BN / TN;
    __shared__ __align__(16) float As[BK][BM + 4];
    __shared__ __align__(16) float Bs[BK][BN + 4];
    const int tid = threadIdx.x;
    const int tx = tid % TX;
    const int ty = tid / TX;
    const int m0 = blockIdx.y * BM;
    const int n0 = blockIdx.x * BN;

    float acc[TM][TN];
#pragma unroll
    for (int i = 0; i < TM; i++)
#pragma unroll
        for (int j = 0; j < TN; j++) acc[i][j] = 0.f;

    for (int k0 = 0; k0 < K; k0 += BK) {
        if (LAYOUT == 2) {              // A in [K,M]
#pragma unroll
            for (int i = 0; i < (BM * BK) / THREADS; i++) {
                int e = tid + i * THREADS;
                int k = e / BM, m = e % BM;
                As[k][m] = A[(size_t)(k0 + k) * M + (m0 + m)];
            }
        } else {                        // A in [M,K]
#pragma unroll
            for (int i = 0; i < (BM * BK) / THREADS; i++) {
                int e = tid + i * THREADS;
                int m = e / BK, k = e % BK;
                As[k][m] = A[(size_t)(m0 + m) * K + (k0 + k)];
            }
        }
        if (LAYOUT == 0) {              // B in [N,K]
#pragma unroll
            for (int i = 0; i < (BN * BK) / THREADS; i++) {
                int e = tid + i * THREADS;
                int n = e / BK, k = e % BK;
                Bs[k][n] = B[(size_t)(n0 + n) * K + (k0 + k)];
            }
        } else {                        // B in [K,N]
#pragma unroll
            for (int i = 0; i < (BN * BK) / THREADS; i++) {
                int e = tid + i * THREADS;
                int k = e / BN, n = e % BN;
                Bs[k][n] = B[(size_t)(k0 + k) * N + (n0 + n)];
            }
        }
        __syncthreads();
#pragma unroll
        for (int kk = 0; kk < BK; kk++) {
            float a[TM], b[TN];
#pragma unroll
            for (int i = 0; i < TM; i += 4) {
                float4 t = *reinterpret_cast<const float4*>(&As[kk][ty * TM + i]);
                a[i] = t.x; a[i + 1] = t.y; a[i + 2] = t.z; a[i + 3] = t.w;
            }
#pragma unroll
            for (int j = 0; j < TN; j += 4) {
                float4 t = *reinterpret_cast<const float4*>(&Bs[kk][tx * TN + j]);
                b[j] = t.x; b[j + 1] = t.y; b[j + 2] = t.z; b[j + 3] = t.w;
            }
#pragma unroll
            for (int i = 0; i < TM; i++)
#pragma unroll
                for (int j = 0; j < TN; j++) acc[i][j] = fmaf(a[i], b[j], acc[i][j]);
        }
        __syncthreads();
    }

#pragma unroll
    for (int i = 0; i < TM; i++) {
        int m = m0 + ty * TM + i;
        float sd = 0.f, rm = 0.f, rs = 1.f;
        if (EPI == 4) { sd = sdecay[m]; rm = rmax[m]; rs = rsum[m]; }
#pragma unroll
        for (int j = 0; j < TN; j++) {
            int n = n0 + tx * TN + j;
            size_t idx = (size_t)m * N + n;
            float v = acc[i][j];
            if (EPI == 1)      { v += bias[n]; v = fmaxf(v, 0.f); }
            else if (EPI == 2) { v += bias[n]; }
            else if (EPI == 3) { v += addmat[idx]; v = fmaxf(v, 0.f); }
            else if (EPI == 4) {
                float w = Wold[idx];
                float p = expf(w - rm) / rs;                 // row softmax of W
                v = w + p * (v * (1.0f / BB)) - sd * w;      // W + wu - sd*W
            }
            C[idx] = v;
        }
    }
}

// ---------------- host launch ----------------
template<typename T>
static float* sym_addr(T& sym) { void* p = nullptr; cudaGetSymbolAddress(&p, sym); return (float*)p; }

extern "C" void kernel_launch(void* const* d_in, const int* in_sizes, int n_in,
                              void* d_out, int out_size) {
    const float* x        = (const float*)d_in[0];
    const float* prev_act = (const float*)d_in[1];
    const float* prev_rec = (const float*)d_in[2];
    const float* dopamine = (const float*)d_in[3];
    const float* serotonin= (const float*)d_in[4];
    const float* gaba     = (const float*)d_in[5];
    const float* W        = (const float*)d_in[6];
    const float* Wr       = (const float*)d_in[7];
    const float* alpha    = (const float*)d_in[8];
    const float* decay    = (const float*)d_in[9];
    const float* gact     = (const float*)d_in[10];
    const float* bact     = (const float*)d_in[11];
    const float* grec     = (const float*)d_in[12];
    const float* brec     = (const float*)d_in[13];
    const float* p1w      = (const float*)d_in[14];
    const float* p1b      = (const float*)d_in[15];
    const float* p2w      = (const float*)d_in[16];
    const float* p2b      = (const float*)d_in[17];
    float* out = (float*)d_out;

    float *h    = sym_addr(g_h),    *nt   = sym_addr(g_nt),   *ma   = sym_addr(g_ma);
    float *as_  = sym_addr(g_as),   *ars  = sym_addr(g_ars);
    float *gsum = sym_addr(g_gsum), *sdec = sym_addr(g_sdec);
    float *rmW  = sym_addr(g_rmW),  *rsW  = sym_addr(g_rsW);
    float *rmR  = sym_addr(g_rmR),  *rsR  = sym_addr(g_rsR);
    float *Wn   = sym_addr(g_Wn),   *Wrn  = sym_addr(g_Wrn);
    float *rec  = sym_addr(g_rec),  *recin= sym_addr(g_recin), *act = sym_addr(g_act);

    // softmaxes + W row stats (independent)
    row_softmax_kernel<<<BB, 256>>>(prev_act, as_);
    row_softmax_kernel<<<BB, 256>>>(prev_rec, ars);
    row_stats_kernel<<<D, 256>>>(W, rmW, rsW);
    row_stats_kernel<<<D, 256>>>(Wr, rmR, rsR);

    // h = relu(prev_act @ p1_w^T + p1_b)
    gemm_kernel<64,128,16,4,8,0,1><<<dim3(D/128, BB/64), 256>>>(
        prev_act, p1w, h, BB, D, D, p1b, nullptr, nullptr, nullptr, nullptr, nullptr);
    // nt = h @ p2_w^T + p2_b
    gemm_kernel<64,128,16,4,8,0,2><<<dim3(N3/128, BB/64), 256>>>(
        h, p2w, nt, BB, N3, D, p2b, nullptr, nullptr, nullptr, nullptr, nullptr);

    // neuromodulators -> mod_alpha, scaled_decay
    zero_kernel<<<D/256, 256>>>(gsum, D);
    neuromod_partial<<<dim3(D/256, 8), 256>>>(nt, dopamine, serotonin, gaba, alpha, ma, gsum);
    sdecay_kernel<<<D/256, 256>>>(gsum, decay, sdec);

    // W_new / Wr_new : corr GEMM (TN, K=512) fused with Hebbian update epilogue
    gemm_kernel<128,128,16,8,8,2,4><<<dim3(D/128, D/128), 256>>>(
        as_, ma, Wn, D, D, BB, nullptr, nullptr, W, rmW, rsW, sdec);
    gemm_kernel<128,128,16,8,8,2,4><<<dim3(D/128, D/128), 256>>>(
        ars, ma, Wrn, D, D, BB, nullptr, nullptr, Wr, rmR, rsR, sdec);

    // rec = prev_act @ Wr_new ; rec_in = LN(rec)
    gemm_kernel<64,128,16,4,8,1,0><<<dim3(D/128, BB/64), 256>>>(
        prev_act, Wrn, rec, BB, D, D, nullptr, nullptr, nullptr, nullptr, nullptr, nullptr);
    layernorm_kernel<<<BB, 256>>>(rec, grec, brec, recin);

    // act = relu(x @ W_new + rec_in) ; out = LN(act)
    gemm_kernel<64,128,16,4,8,1,3><<<dim3(D/128, BB/64), 256>>>(
        x, Wn, act, BB, D, D, nullptr, recin, nullptr, nullptr, nullptr, nullptr);
    layernorm_kernel<<<BB, 256>>>(act, gact, bact, out);
}